// round 15
// baseline (speedup 1.0000x reference)
#include <cuda_runtime.h>
#include <cuda_bf16.h>
#include <math.h>
#include <stdint.h>

// ---------------------------------------------------------------------------
// ENL transformer block (Performer / FAVOR+), mma.sync bf16-split GEMMs.
// Round-9 proven GEMM core + preconverted hi/lo operands (lean staging).
// B=8, C=256, N=4096 tokens/batch, F=256, MLP hidden=1024.
// ---------------------------------------------------------------------------

#define TOK   4096
#define BAT   8
#define DIMC  256
#define HID   1024
#define MTOT  (BAT * TOK)

typedef unsigned long long ull;
typedef __nv_bfloat16 bf16;

// ------------------------------ scratch ------------------------------------
__device__ float g_t   [(size_t)MTOT * DIMC];
__device__ float g_qkv [(size_t)MTOT * 768];          // q|k|v per row
__device__ float g_qkp [(size_t)2 * MTOT * DIMC];     // qp | kp
__device__ float g_ctx [(size_t)BAT * DIMC * DIMC];
__device__ float g_ksum[BAT * DIMC];
__device__ float g_dqk [(size_t)2 * MTOT];            // dq | dk
__device__ float g_di  [(size_t)MTOT];
__device__ float g_bqkv[768];
// bf16 hi/lo operand buffers
__device__ bf16 g_hh  [(size_t)MTOT * DIMC], g_hl  [(size_t)MTOT * DIMC];
__device__ bf16 g_qknh[(size_t)2 * MTOT * DIMC], g_qknl[(size_t)2 * MTOT * DIMC];
__device__ bf16 g_qkph[(size_t)2 * MTOT * DIMC], g_qkpl[(size_t)2 * MTOT * DIMC];
__device__ bf16 g_h2h [(size_t)MTOT * DIMC], g_h2l [(size_t)MTOT * DIMC];
__device__ bf16 g_mh  [(size_t)MTOT * HID],  g_ml  [(size_t)MTOT * HID];
__device__ bf16 g_wvh [768 * DIMC], g_wvl [768 * DIMC];   // qkv weights concat
__device__ bf16 g_pjh [DIMC * DIMC], g_pjl [DIMC * DIMC];
__device__ bf16 g_w1h [HID * DIMC],  g_w1l [HID * DIMC];
__device__ bf16 g_w2h [DIMC * HID],  g_w2l [DIMC * HID];
__device__ bf16 g_cxh [BAT * DIMC * DIMC], g_cxl [BAT * DIMC * DIMC];

// ---------------------------- packed fp32x2 (k_atb) ------------------------
__device__ __forceinline__ void ffma2(ull& d, ull a, ull b) {
    asm("fma.rn.f32x2 %0, %1, %2, %0;" : "+l"(d) : "l"(a), "l"(b));
}
__device__ __forceinline__ ull pack2f(float x) {
    ull r; asm("mov.b64 %0, {%1, %1};" : "=l"(r) : "f"(x)); return r;
}
union U2 { ull u; float2 f; };

// ---------------------------- bf16 helpers ---------------------------------
__device__ __forceinline__ uint32_t bf2pack(float lo, float hi) {
    uint32_t r;
    asm("cvt.rn.bf16x2.f32 %0, %1, %2;" : "=r"(r) : "f"(hi), "f"(lo));
    return r;
}
__device__ __forceinline__ void split_one(float v, bf16* hp, bf16* lp) {
    bf16 h = __float2bfloat16(v);
    *hp = h;
    *lp = __float2bfloat16(v - __bfloat162float(h));
}

// mma.sync m16n8k16 row.col f32 += bf16*bf16
__device__ __forceinline__ void mma16816v(float* c, const uint32_t* a,
                                          const uint32_t* b) {
    asm volatile(
        "mma.sync.aligned.m16n8k16.row.col.f32.bf16.bf16.f32 "
        "{%0,%1,%2,%3}, {%4,%5,%6,%7}, {%8,%9}, {%0,%1,%2,%3};"
        : "+f"(c[0]), "+f"(c[1]), "+f"(c[2]), "+f"(c[3])
        : "r"(a[0]), "r"(a[1]), "r"(a[2]), "r"(a[3]), "r"(b[0]), "r"(b[1]));
}

#define BKP 24   // smem row stride (bf16): conflict-free fragment reads

__device__ __forceinline__ void ld_afrag(uint32_t af[4][4], const bf16* S,
                                         int ar, int ac) {
    #pragma unroll
    for (int mt = 0; mt < 4; mt++) {
        const bf16* p = S + (ar + mt * 16) * BKP + ac;
        af[mt][0] = *(const uint32_t*)(p);
        af[mt][1] = *(const uint32_t*)(p + 8 * BKP);
        af[mt][2] = *(const uint32_t*)(p + 8);
        af[mt][3] = *(const uint32_t*)(p + 8 * BKP + 8);
    }
}
__device__ __forceinline__ void ld_bfrag(uint32_t bf_[4][2], const bf16* S,
                                         int br, int ac) {
    #pragma unroll
    for (int nt = 0; nt < 4; nt++) {
        const bf16* p = S + (br + nt * 8) * BKP + ac;
        bf_[nt][0] = *(const uint32_t*)(p);
        bf_[nt][1] = *(const uint32_t*)(p + 8);
    }
}
__device__ __forceinline__ void mma_all(float acc[16][4],
                                        uint32_t a[4][4], uint32_t b[4][2]) {
    #pragma unroll
    for (int mt = 0; mt < 4; mt++)
        #pragma unroll
        for (int nt = 0; nt < 4; nt++)
            mma16816v(acc[mt * 4 + nt], a[mt], b[nt]);
}

// ---------------------------------------------------------------------------
// GEMM: C[M,N] = epi( A[M,K] @ W[N,K]^T ), operands preconverted bf16 hi/lo.
// Round-9 core: CTA 128x128, BK=16, 8 warps (64x32), static smem, BKP=24,
// double buffer, 1 sync/chunk. 3 passes: Ah*Wh + Ah*Wl + Al*Wh.
// modes: 0 bias | 1 bias+gelu | 2 bias+res | 3 featuremap | 4 res+aux*acc
// ---------------------------------------------------------------------------
__global__ void __launch_bounds__(256, 2) k_gemm_mma(
    const bf16* __restrict__ Ah, const bf16* __restrict__ Al,
    const bf16* __restrict__ Wh, const bf16* __restrict__ Wl,
    const float* __restrict__ bias, float* __restrict__ outF,
    bf16* __restrict__ outHi, bf16* __restrict__ outLo,
    int K, int N, int mode,
    const float* __restrict__ aux, const float* __restrict__ res,
    int wbatch)
{
    __shared__ bf16 sAh[2][128 * BKP], sAl[2][128 * BKP];
    __shared__ bf16 sWh[2][128 * BKP], sWl[2][128 * BKP];

    int tid = threadIdx.x;
    int lane = tid & 31, wid = tid >> 5;
    int wm = wid & 1, wn = wid >> 1;
    int m0 = blockIdx.y * 128, n0 = blockIdx.x * 128;
    size_t wb_off = wbatch ? (size_t)(m0 / TOK) * (size_t)wbatch : 0;

    float acc[16][4];
    #pragma unroll
    for (int i = 0; i < 16; i++)
        #pragma unroll
        for (int j = 0; j < 4; j++) acc[i][j] = 0.f;

    // staging: 4 streams x 64 threads; thread handles rows 2tr, 2tr+1 (32B each)
    int s = tid >> 6, tr = tid & 63;
    int r0 = tr * 2, r1 = tr * 2 + 1;
    const bf16* gbase = (s == 0) ? Ah + (size_t)m0 * K
                      : (s == 1) ? Al + (size_t)m0 * K
                      : (s == 2) ? Wh + wb_off + (size_t)n0 * K
                                 : Wl + wb_off + (size_t)n0 * K;
    bf16* d0 = (s == 0) ? sAh[0] : (s == 1) ? sAl[0] : (s == 2) ? sWh[0] : sWl[0];
    bf16* d1 = (s == 0) ? sAh[1] : (s == 1) ? sAl[1] : (s == 2) ? sWh[1] : sWl[1];
    const bf16* gr0 = gbase + (size_t)r0 * K;
    const bf16* gr1 = gbase + (size_t)r1 * K;

    // prologue: chunk 0 -> buffer 0
    uint4 v0 = *(const uint4*)(gr0);
    uint4 v1 = *(const uint4*)(gr0 + 8);
    uint4 v2 = *(const uint4*)(gr1);
    uint4 v3 = *(const uint4*)(gr1 + 8);
    *(uint4*)(d0 + r0 * BKP) = v0; *(uint4*)(d0 + r0 * BKP + 8) = v1;
    *(uint4*)(d0 + r1 * BKP) = v2; *(uint4*)(d0 + r1 * BKP + 8) = v3;
    __syncthreads();

    int ar = wm * 64 + (lane >> 2);
    int br = wn * 32 + (lane >> 2);
    int ac = (lane & 3) * 2;
    const int nc = K >> 4;

    for (int c = 0; c < nc; c++) {
        int buf = c & 1;
        bool pf = (c + 1 < nc);
        if (pf) {
            int kc = (c + 1) * 16;
            v0 = *(const uint4*)(gr0 + kc);
            v1 = *(const uint4*)(gr0 + kc + 8);
            v2 = *(const uint4*)(gr1 + kc);
            v3 = *(const uint4*)(gr1 + kc + 8);
        }
        {
            uint32_t af[4][4], bf_[4][2];
            ld_afrag(af, sAh[buf], ar, ac);       // A-hi
            ld_bfrag(bf_, sWh[buf], br, ac);      // W-hi
            mma_all(acc, af, bf_);                // hh
            ld_bfrag(bf_, sWl[buf], br, ac);      // W-lo (A-hi reused)
            mma_all(acc, af, bf_);
            ld_afrag(af, sAl[buf], ar, ac);       // A-lo
            ld_bfrag(bf_, sWh[buf], br, ac);      // W-hi
            mma_all(acc, af, bf_);
        }
        if (pf) {
            bf16* dd = (c & 1) ? d0 : d1;         // next buffer
            *(uint4*)(dd + r0 * BKP) = v0; *(uint4*)(dd + r0 * BKP + 8) = v1;
            *(uint4*)(dd + r1 * BKP) = v2; *(uint4*)(dd + r1 * BKP + 8) = v3;
        }
        __syncthreads();
    }

    // epilogue
    #pragma unroll
    for (int mt = 0; mt < 4; mt++) {
        #pragma unroll
        for (int half = 0; half < 2; half++) {
            int m = m0 + wm * 64 + mt * 16 + (lane >> 2) + half * 8;
            float am = (mode >= 3) ? aux[m] : 0.f;
            #pragma unroll
            for (int nt = 0; nt < 4; nt++) {
                int n = n0 + wn * 32 + nt * 8 + (lane & 3) * 2;
                float x0 = acc[mt * 4 + nt][half * 2 + 0];
                float x1 = acc[mt * 4 + nt][half * 2 + 1];
                if (mode == 0)      { x0 += bias[n]; x1 += bias[n + 1]; }
                else if (mode == 1) { x0 += bias[n]; x1 += bias[n + 1];
                                      x0 *= normcdff(x0); x1 *= normcdff(x1); }
                else if (mode == 2) { x0 += bias[n]     + res[(size_t)m * N + n];
                                      x1 += bias[n + 1] + res[(size_t)m * N + n + 1]; }
                else if (mode == 3) { x0 = 0.0625f * (expf(x0 - am) + 1e-4f);
                                      x1 = 0.0625f * (expf(x1 - am) + 1e-4f); }
                else                { x0 = res[(size_t)m * N + n]     + am * x0;
                                      x1 = res[(size_t)m * N + n + 1] + am * x1; }
                if (outF)
                    *(float2*)&outF[(size_t)m * N + n] = make_float2(x0, x1);
                if (outHi) {
                    bf16 h0 = __float2bfloat16(x0);
                    bf16 h1 = __float2bfloat16(x1);
                    uint32_t hp = ((uint32_t)__bfloat16_as_ushort(h1) << 16)
                                | __bfloat16_as_ushort(h0);
                    uint32_t lp = bf2pack(x0 - __bfloat162float(h0),
                                          x1 - __bfloat162float(h1));
                    *(uint32_t*)&outHi[(size_t)m * N + n] = hp;
                    *(uint32_t*)&outLo[(size_t)m * N + n] = lp;
                }
            }
        }
    }
}

// ---------------------------------------------------------------------------
// one-shot conversions: qkv weights (concat) + proj + w1 + w2 + qkv biases
// ---------------------------------------------------------------------------
__global__ void k_cvt_all(
    const float* __restrict__ wq, const float* __restrict__ wk,
    const float* __restrict__ wa, const float* __restrict__ proj,
    const float* __restrict__ w1, const float* __restrict__ w2,
    const float* __restrict__ bq, const float* __restrict__ bk,
    const float* __restrict__ ba,
    bf16* __restrict__ wvh, bf16* __restrict__ wvl,
    bf16* __restrict__ pjh, bf16* __restrict__ pjl,
    bf16* __restrict__ w1h, bf16* __restrict__ w1l,
    bf16* __restrict__ w2h, bf16* __restrict__ w2l,
    float* __restrict__ bqkv)
{
    int i = blockIdx.x * 256 + threadIdx.x;
    if (i < 196608) {                      // wq|wk|wa -> concat [768][256]
        const float* src = (i < 65536) ? wq : (i < 131072) ? wk : wa;
        split_one(src[i & 65535], &wvh[i], &wvl[i]);
    } else if (i < 262144) {
        int li = i - 196608; split_one(proj[li], &pjh[li], &pjl[li]);
    } else if (i < 524288) {
        int li = i - 262144; split_one(w1[li], &w1h[li], &w1l[li]);
    } else if (i < 786432) {
        int li = i - 524288; split_one(w2[li], &w2h[li], &w2l[li]);
    } else if (i < 787200) {
        int li = i - 786432;
        bqkv[li] = (li < 256) ? bq[li] : (li < 512) ? bk[li - 256] : ba[li - 512];
    }
}

__global__ void k_cvt(const float* __restrict__ src, bf16* __restrict__ hi,
                      bf16* __restrict__ lo, int n)
{
    int i = blockIdx.x * 256 + threadIdx.x;
    if (i < n) split_one(src[i], &hi[i], &lo[i]);
}

// ---------------------------------------------------------------------------
// K1: transpose [B,C,N] -> [B,N,C]; t = shortcut fp32, h = LN1 bf16 hi/lo
// ---------------------------------------------------------------------------
__global__ void __launch_bounds__(256) k_tr_ln(
    const float* __restrict__ x, const float* __restrict__ g,
    const float* __restrict__ bta, float* __restrict__ t,
    bf16* __restrict__ hh, bf16* __restrict__ hl)
{
    __shared__ float tile[32][257];
    int b  = blockIdx.y;
    int n0 = blockIdx.x * 32;
    const float* xb = x + (size_t)b * DIMC * TOK;
    int tx = threadIdx.x & 31, ty = threadIdx.x >> 5;
    #pragma unroll 4
    for (int cc = 0; cc < 32; cc++) {
        int c = cc * 8 + ty;
        tile[tx][c] = xb[(size_t)c * TOK + n0 + tx];
    }
    __syncthreads();
    for (int rep = 0; rep < 4; rep++) {
        int nl = ty + rep * 8;
        float v[8], s = 0.f, sq = 0.f;
        #pragma unroll
        for (int i = 0; i < 8; i++) {
            v[i] = tile[nl][tx + 32 * i];
            s += v[i]; sq += v[i] * v[i];
        }
        #pragma unroll
        for (int o = 16; o; o >>= 1) {
            s  += __shfl_xor_sync(~0u, s,  o);
            sq += __shfl_xor_sync(~0u, sq, o);
        }
        float mu  = s * (1.f / DIMC);
        float var = sq * (1.f / DIMC) - mu * mu;
        float inv = rsqrtf(var + 1e-5f);
        size_t base = ((size_t)b * TOK + n0 + nl) * DIMC;
        #pragma unroll
        for (int i = 0; i < 8; i++) {
            int c = tx + 32 * i;
            t[base + c] = v[i];
            float hv = (v[i] - mu) * inv * g[c] + bta[c];
            split_one(hv, &hh[base + c], &hl[base + c]);
        }
    }
}

// ---------------------------------------------------------------------------
// LayerNorm2: t fp32 -> h2 bf16 hi/lo
// ---------------------------------------------------------------------------
__global__ void __launch_bounds__(256) k_ln(
    const float* __restrict__ t, const float* __restrict__ g,
    const float* __restrict__ bta, bf16* __restrict__ hh, bf16* __restrict__ hl)
{
    int tok  = blockIdx.x * 8 + (threadIdx.x >> 5);
    int lane = threadIdx.x & 31;
    const float* row = t + (size_t)tok * DIMC;
    float v[8], s = 0.f, sq = 0.f;
    #pragma unroll
    for (int i = 0; i < 8; i++) {
        v[i] = row[lane + 32 * i];
        s += v[i]; sq += v[i] * v[i];
    }
    #pragma unroll
    for (int o = 16; o; o >>= 1) {
        s  += __shfl_xor_sync(~0u, s,  o);
        sq += __shfl_xor_sync(~0u, sq, o);
    }
    float mu  = s * (1.f / DIMC);
    float var = sq * (1.f / DIMC) - mu * mu;
    float inv = rsqrtf(var + 1e-5f);
    size_t base = (size_t)tok * DIMC;
    #pragma unroll
    for (int i = 0; i < 8; i++) {
        int c = lane + 32 * i;
        float hv = (v[i] - mu) * inv * g[c] + bta[c];
        split_one(hv, &hh[base + c], &hl[base + c]);
    }
}

// ---------------------------------------------------------------------------
// L2-normalize q,k (from qkv buffer, pitch 768) -> qn|kn bf16 hi/lo + diag
// ---------------------------------------------------------------------------
__global__ void __launch_bounds__(256) k_norm(
    const float* __restrict__ qkv,
    bf16* __restrict__ qknh, bf16* __restrict__ qknl,
    float* __restrict__ dqk)
{
    int tok  = blockIdx.x * 8 + (threadIdx.x >> 5);
    int lane = threadIdx.x & 31;
    for (int s2 = 0; s2 < 2; s2++) {
        const float* row = qkv + (size_t)tok * 768 + s2 * 256;
        size_t obase = ((size_t)s2 * MTOT + tok) * DIMC;
        float v[8], sq = 0.f;
        #pragma unroll
        for (int i = 0; i < 8; i++) {
            v[i] = row[lane + 32 * i];
            sq += v[i] * v[i];
        }
        #pragma unroll
        for (int o = 16; o; o >>= 1) sq += __shfl_xor_sync(~0u, sq, o);
        float nrm = sqrtf(sq);
        float sc  = 1.0f / fmaxf(nrm, 5e-5f);
        #pragma unroll
        for (int i = 0; i < 8; i++) {
            int c = lane + 32 * i;
            split_one(v[i] * sc, &qknh[obase + c], &qknl[obase + c]);
        }
        if (lane == 0) dqk[(size_t)s2 * MTOT + tok] = 0.5f * sq * sc * sc;
    }
}

// ---------------------------------------------------------------------------
// ctx^T[b][c][f] += sum_n v[b][n][c]*kp[b][n][f]
// 128x128 tile, 8x8 microtile f32x2, ksplit 8. V pitch 768 (col off 512).
// ---------------------------------------------------------------------------
__global__ void __launch_bounds__(256) k_atb(
    const float* __restrict__ QKV, const float* __restrict__ KP,
    float* __restrict__ CT)
{
    __shared__ __align__(16) float Vs[16][132];
    __shared__ __align__(16) float Ks[16][132];
    int b  = blockIdx.z >> 3;
    int ks = blockIdx.z & 7;
    int c0 = blockIdx.y * 128;
    int f0 = blockIdx.x * 128;
    const float* Vp = QKV + (size_t)b * TOK * 768 + 512;
    const float* Kp = KP  + (size_t)b * TOK * DIMC;
    int tid = threadIdx.x;
    int sr = tid >> 4, sc = (tid & 15) * 8;
    int tx = tid & 15, ty = tid >> 4;
    ull acc[8][4];
    #pragma unroll
    for (int i = 0; i < 8; i++)
        #pragma unroll
        for (int j = 0; j < 4; j++) acc[i][j] = 0ull;

    int nbeg = ks * (TOK / 8);
    for (int nt = 0; nt < TOK / 8; nt += 16) {
        int n = nbeg + nt + sr;
        *(float4*)&Vs[sr][sc]     = *(const float4*)&Vp[(size_t)n * 768 + c0 + sc];
        *(float4*)&Vs[sr][sc + 4] = *(const float4*)&Vp[(size_t)n * 768 + c0 + sc + 4];
        *(float4*)&Ks[sr][sc]     = *(const float4*)&Kp[(size_t)n * DIMC + f0 + sc];
        *(float4*)&Ks[sr][sc + 4] = *(const float4*)&Kp[(size_t)n * DIMC + f0 + sc + 4];
        __syncthreads();
        #pragma unroll
        for (int kk = 0; kk < 16; kk++) {
            float4 a0 = *(const float4*)&Vs[kk][ty * 4];
            float4 a1 = *(const float4*)&Vs[kk][64 + ty * 4];
            ulonglong2 b0 = *(const ulonglong2*)&Ks[kk][tx * 4];
            ulonglong2 b1 = *(const ulonglong2*)&Ks[kk][64 + tx * 4];
            float a[8] = {a0.x, a0.y, a0.z, a0.w, a1.x, a1.y, a1.z, a1.w};
            ull B[4] = {b0.x, b0.y, b1.x, b1.y};
            #pragma unroll
            for (int i = 0; i < 8; i++) {
                ull ai = pack2f(a[i]);
                #pragma unroll
                for (int j = 0; j < 4; j++) ffma2(acc[i][j], ai, B[j]);
            }
        }
        __syncthreads();
    }
    float* Cb = CT + (size_t)b * DIMC * DIMC;
    #pragma unroll
    for (int i = 0; i < 8; i++) {
        int cr = c0 + ((i < 4) ? (ty * 4 + i) : (64 + ty * 4 + i - 4));
        #pragma unroll
        for (int j = 0; j < 4; j++) {
            int fc = f0 + ((j < 2) ? (tx * 4 + 2 * j) : (64 + tx * 4 + 2 * (j - 2)));
            U2 u; u.u = acc[i][j];
            atomicAdd(&Cb[(size_t)cr * DIMC + fc],     u.f.x);
            atomicAdd(&Cb[(size_t)cr * DIMC + fc + 1], u.f.y);
        }
    }
}

// ---------------------------------------------------------------------------
// small helpers
// ---------------------------------------------------------------------------
__global__ void k_zero(float* __restrict__ p, int n)
{
    int i = blockIdx.x * 256 + threadIdx.x;
    if (i < n) p[i] = 0.f;
}

__global__ void __launch_bounds__(256) k_colsum(
    const float* __restrict__ kp, float* __restrict__ ksum)
{
    int b = blockIdx.y, ch = blockIdx.x;
    int f = threadIdx.x;
    const float* base = kp + ((size_t)b * TOK + ch * 128) * DIMC + f;
    float s = 0.f;
    #pragma unroll 8
    for (int i = 0; i < 128; i++) s += base[(size_t)i * DIMC];
    atomicAdd(&ksum[b * DIMC + f], s);
}

__global__ void __launch_bounds__(256) k_dinv(
    const float* __restrict__ qp, const float* __restrict__ ksum,
    float* __restrict__ di)
{
    int tok  = blockIdx.x * 8 + (threadIdx.x >> 5);
    int lane = threadIdx.x & 31;
    int b = tok >> 12;
    const float* row = qp + (size_t)tok * DIMC;
    const float* ks  = ksum + b * DIMC;
    float s = 0.f;
    #pragma unroll
    for (int i = 0; i < 8; i++) { int c = lane + 32 * i; s += row[c] * ks[c]; }
    #pragma unroll
    for (int o = 16; o; o >>= 1) s += __shfl_xor_sync(~0u, s, o);
    if (lane == 0) di[tok] = 1.0f / s;
}

__global__ void __launch_bounds__(256) k_out_tr(
    const float* __restrict__ t, float* __restrict__ out)
{
    __shared__ float tile[32][33];
    int b  = blockIdx.z;
    int n0 = blockIdx.x * 32;
    int c0 = blockIdx.y * 32;
    int tx = threadIdx.x & 31, ty = threadIdx.x >> 5;
    #pragma unroll
    for (int i = 0; i < 32; i += 8)
        tile[ty + i][tx] = t[((size_t)b * TOK + n0 + ty + i) * DIMC + c0 + tx];
    __syncthreads();
    #pragma unroll
    for (int i = 0; i < 32; i += 8)
        out[((size_t)b * DIMC + c0 + ty + i) * TOK + n0 + tx] = tile[tx][ty + i];
}

// ---------------------------------------------------------------------------
// host launch
// ---------------------------------------------------------------------------
#define SYM(var, sym) cudaGetSymbolAddress((void**)&var, sym)

extern "C" void kernel_launch(void* const* d_in, const int* in_sizes, int n_in,
                              void* d_out, int out_size)
{
    const float* x    = (const float*)d_in[0];
    const float* proj = (const float*)d_in[1];
    const float* wq   = (const float*)d_in[2];
    const float* bq   = (const float*)d_in[3];
    const float* wk   = (const float*)d_in[4];
    const float* bk   = (const float*)d_in[5];
    const float* wa   = (const float*)d_in[6];
    const float* ba   = (const float*)d_in[7];
    const float* g1   = (const float*)d_in[8];
    const float* b1   = (const float*)d_in[9];
    const float* g2   = (const float*)d_in[10];
    const float* b2   = (const float*)d_in[11];
    const float* w1   = (const float*)d_in[12];
    const float* fb1  = (const float*)d_in[13];
    const float* w2   = (const float*)d_in[14];
    const float* fb2  = (const float*)d_in[15];
    float* out = (float*)d_out;
    (void)in_sizes; (void)n_in; (void)out_size;

    float *t, *qkv, *qkp, *ctx, *ksum, *dqk, *di, *bqkv;
    bf16 *hh, *hl, *qknh, *qknl, *qkph, *qkpl, *h2h, *h2l, *mh, *ml;
    bf16 *wvh, *wvl, *pjh, *pjl, *w1h, *w1l, *w2h, *w2l, *cxh, *cxl;
    SYM(t, g_t); SYM(qkv, g_qkv); SYM(qkp, g_qkp); SYM(ctx, g_ctx);
    SYM(ksum, g_ksum); SYM(dqk, g_dqk); SYM(di, g_di); SYM(bqkv, g_bqkv);
    SYM(hh, g_hh); SYM(hl, g_hl);
    SYM(qknh, g_qknh); SYM(qknl, g_qknl);
    SYM(qkph, g_qkph); SYM(qkpl, g_qkpl);
    SYM(h2h, g_h2h); SYM(h2l, g_h2l); SYM(mh, g_mh); SYM(ml, g_ml);
    SYM(wvh, g_wvh); SYM(wvl, g_wvl); SYM(pjh, g_pjh); SYM(pjl, g_pjl);
    SYM(w1h, g_w1h); SYM(w1l, g_w1l); SYM(w2h, g_w2h); SYM(w2l, g_w2l);
    SYM(cxh, g_cxh); SYM(cxl, g_cxl);

    // 0. all weight conversions in one launch
    k_cvt_all<<<3075, 256>>>(wq, wk, wa, proj, w1, w2, bq, bk, ba,
                             wvh, wvl, pjh, pjl, w1h, w1l, w2h, w2l, bqkv);

    // 1. transpose + LN1
    k_tr_ln<<<dim3(TOK / 32, BAT), 256>>>(x, g1, b1, t, hh, hl);

    // 2. fused QKV projection (N=768) -> qkv
    k_gemm_mma<<<dim3(6, MTOT / 128), 256>>>(hh, hl, wvh, wvl, bqkv, qkv,
                                             nullptr, nullptr,
                                             DIMC, 768, 0, nullptr, nullptr, 0);

    // 3. L2 normalize q,k -> qn|kn hi/lo + diag
    k_norm<<<MTOT / 8, 256>>>(qkv, qknh, qknl, dqk);

    // 4. fused feature maps (M = 2*MTOT) -> qkp fp32 + hi/lo
    k_gemm_mma<<<dim3(2, 2 * MTOT / 128), 256>>>(qknh, qknl, pjh, pjl, nullptr,
                                                 qkp, qkph, qkpl,
                                                 DIMC, DIMC, 3, dqk, nullptr, 0);

    // 5. k_sum and ctx^T, then ctx -> bf16 hi/lo
    k_zero<<<(BAT * DIMC * DIMC + 255) / 256, 256>>>(ctx, BAT * DIMC * DIMC);
    k_zero<<<(BAT * DIMC + 255) / 256, 256>>>(ksum, BAT * DIMC);
    k_colsum<<<dim3(32, BAT), 256>>>(qkp + (size_t)MTOT * DIMC, ksum);
    k_atb<<<dim3(2, 2, BAT * 8), 256>>>(qkv, qkp + (size_t)MTOT * DIMC, ctx);
    k_cvt<<<BAT * DIMC * DIMC / 256, 256>>>(ctx, cxh, cxl, BAT * DIMC * DIMC);

    // 6. D_inv
    k_dinv<<<MTOT / 8, 256>>>(qkp, ksum, di);

    // 7. out = res + D_inv * (qp @ ctx^T^T)  (per-batch W = ctx)
    k_gemm_mma<<<dim3(2, MTOT / 128), 256>>>(qkph, qkpl, cxh, cxl, nullptr, t,
                                             nullptr, nullptr,
                                             DIMC, DIMC, 4, di, t, DIMC * DIMC);

    // 8. LN2 + MLP
    k_ln<<<MTOT / 8, 256>>>(t, g2, b2, h2h, h2l);
    k_gemm_mma<<<dim3(8, MTOT / 128), 256>>>(h2h, h2l, w1h, w1l, fb1, nullptr,
                                             mh, ml, DIMC, HID, 1,
                                             nullptr, nullptr, 0);
    k_gemm_mma<<<dim3(2, MTOT / 128), 256>>>(mh, ml, w2h, w2l, fb2, t,
                                             nullptr, nullptr, HID, DIMC, 2,
                                             nullptr, t, 0);

    // 9. transpose back
    k_out_tr<<<dim3(TOK / 32, DIMC / 32, BAT), 256>>>(t, out);
}

// round 16
// speedup vs baseline: 1.3139x; 1.3139x over previous
#include <cuda_runtime.h>
#include <cuda_bf16.h>
#include <math.h>
#include <stdint.h>

// ---------------------------------------------------------------------------
// ENL transformer block (Performer / FAVOR+), mma.sync bf16-split GEMMs.
// Round-9 core (static smem, BK=16, BKP=24, fp32-load staging) with
// ldmatrix fragment loads (compile-time-immediate addressing).
// B=8, C=256, N=4096 tokens/batch, F=256, MLP hidden=1024.
// ---------------------------------------------------------------------------

#define TOK   4096
#define BAT   8
#define DIMC  256
#define HID   1024
#define MTOT  (BAT * TOK)

typedef unsigned long long ull;
typedef __nv_bfloat16 bf16;

// ------------------------------ scratch ------------------------------------
__device__ float g_t  [(size_t)MTOT * DIMC];
__device__ float g_h  [(size_t)MTOT * DIMC];
__device__ float g_q  [(size_t)MTOT * DIMC];
__device__ float g_k  [(size_t)MTOT * DIMC];
__device__ float g_v  [(size_t)MTOT * DIMC];
__device__ float g_qp [(size_t)MTOT * DIMC];
__device__ float g_kp [(size_t)MTOT * DIMC];
__device__ float g_m  [(size_t)MTOT * HID];
__device__ float g_ctx[(size_t)BAT * DIMC * DIMC];
__device__ float g_ksum[BAT * DIMC];
__device__ float g_dq [(size_t)MTOT];
__device__ float g_dk [(size_t)MTOT];
__device__ float g_di [(size_t)MTOT];

// ---------------------------- packed fp32x2 (k_atb) ------------------------
__device__ __forceinline__ void ffma2(ull& d, ull a, ull b) {
    asm("fma.rn.f32x2 %0, %1, %2, %0;" : "+l"(d) : "l"(a), "l"(b));
}
__device__ __forceinline__ ull pack2f(float x) {
    ull r; asm("mov.b64 %0, {%1, %1};" : "=l"(r) : "f"(x)); return r;
}
union U2 { ull u; float2 f; };

// ---------------------------- bf16 helpers ---------------------------------
__device__ __forceinline__ uint32_t bf2pack(float lo, float hi) {
    uint32_t r;
    asm("cvt.rn.bf16x2.f32 %0, %1, %2;" : "=r"(r) : "f"(hi), "f"(lo));
    return r;
}
__device__ __forceinline__ uint32_t smem_u32(const void* p) {
    uint32_t a;
    asm("{ .reg .u64 t; cvta.to.shared.u64 t, %1; cvt.u32.u64 %0, t; }"
        : "=r"(a) : "l"(p));
    return a;
}

// mma.sync m16n8k16 row.col f32 += bf16*bf16
__device__ __forceinline__ void mma16816v(float* c, const uint32_t* a,
                                          const uint32_t* b) {
    asm volatile(
        "mma.sync.aligned.m16n8k16.row.col.f32.bf16.bf16.f32 "
        "{%0,%1,%2,%3}, {%4,%5,%6,%7}, {%8,%9}, {%0,%1,%2,%3};"
        : "+f"(c[0]), "+f"(c[1]), "+f"(c[2]), "+f"(c[3])
        : "r"(a[0]), "r"(a[1]), "r"(a[2]), "r"(a[3]), "r"(b[0]), "r"(b[1]));
}

__device__ __forceinline__ void ldsm4(uint32_t r[4], uint32_t addr) {
    asm volatile(
        "ldmatrix.sync.aligned.m8n8.x4.shared.b16 {%0,%1,%2,%3}, [%4];"
        : "=r"(r[0]), "=r"(r[1]), "=r"(r[2]), "=r"(r[3]) : "r"(addr));
}

__device__ __forceinline__ void mma_all(float acc[16][4],
                                        uint32_t a[4][4], uint32_t b[4][2]) {
    #pragma unroll
    for (int mt = 0; mt < 4; mt++)
        #pragma unroll
        for (int nt = 0; nt < 4; nt++)
            mma16816v(acc[mt * 4 + nt], a[mt], b[nt]);
}

// ---------------------------------------------------------------------------
// GEMM: C[M,N] = epi( A[M,K] @ W[N,K]^T ), bf16 hi/lo 3-pass split.
// CTA 128x128, BK=16, 8 warps (warp tile 64x32), static smem BKP=24 (48B rows,
// ldmatrix-conflict-free), double buffer, ldmatrix frag loads, 1 sync/chunk.
// modes: 0 bias | 1 bias+gelu | 2 bias+res | 3 featuremap | 4 res+aux*acc
// ---------------------------------------------------------------------------
#define BKP 24

__device__ __forceinline__ void split_store(bf16* hi, bf16* lo,
                                            int off, float4 v) {
    bf16 h0 = __float2bfloat16(v.x);
    bf16 h1 = __float2bfloat16(v.y);
    bf16 h2 = __float2bfloat16(v.z);
    bf16 h3 = __float2bfloat16(v.w);
    float l0 = v.x - __bfloat162float(h0);
    float l1 = v.y - __bfloat162float(h1);
    float l2 = v.z - __bfloat162float(h2);
    float l3 = v.w - __bfloat162float(h3);
    uint32_t hp0 = ((uint32_t)__bfloat16_as_ushort(h1) << 16) | __bfloat16_as_ushort(h0);
    uint32_t hp1 = ((uint32_t)__bfloat16_as_ushort(h3) << 16) | __bfloat16_as_ushort(h2);
    *(uint2*)(hi + off) = make_uint2(hp0, hp1);
    *(uint2*)(lo + off) = make_uint2(bf2pack(l0, l1), bf2pack(l2, l3));
}

// B-frag pairing (round-11 verified): x4 over 16 W-rows gives
// r0=(n0-7,klo) r1=(n8-15,klo) r2=(n0-7,khi) r3=(n8-15,khi)
#define LD_B2(bb, i0, i1, addr) do {                          \
    uint32_t t4_[4];                                          \
    ldsm4(t4_, (addr));                                       \
    bb[i0][0] = t4_[0]; bb[i0][1] = t4_[2];                   \
    bb[i1][0] = t4_[1]; bb[i1][1] = t4_[3];                   \
} while (0)

// one chunk of compute at compile-time buffer byte offset BOFF
#define GEMM_CHUNK(BOFF) do {                                 \
    uint32_t ah[4][4], bb[4][2];                              \
    ldsm4(ah[0], aAH + (BOFF));                               \
    ldsm4(ah[1], aAH + (BOFF) + 768);                         \
    ldsm4(ah[2], aAH + (BOFF) + 1536);                        \
    ldsm4(ah[3], aAH + (BOFF) + 2304);                        \
    LD_B2(bb, 0, 1, aWH + (BOFF));                            \
    LD_B2(bb, 2, 3, aWH + (BOFF) + 768);                      \
    mma_all(acc, ah, bb);                 /* Ahi*Whi */       \
    LD_B2(bb, 0, 1, aWL + (BOFF));                            \
    LD_B2(bb, 2, 3, aWL + (BOFF) + 768);                      \
    mma_all(acc, ah, bb);                 /* Ahi*Wlo */       \
    ldsm4(ah[0], aAL + (BOFF));                               \
    ldsm4(ah[1], aAL + (BOFF) + 768);                         \
    ldsm4(ah[2], aAL + (BOFF) + 1536);                        \
    ldsm4(ah[3], aAL + (BOFF) + 2304);                        \
    LD_B2(bb, 0, 1, aWH + (BOFF));                            \
    LD_B2(bb, 2, 3, aWH + (BOFF) + 768);                      \
    mma_all(acc, ah, bb);                 /* Alo*Whi */       \
} while (0)

#define STAGE_STORE(AH, AL, WH, WL) do {                      \
    split_store(AH, AL, soff0, va0);                          \
    split_store(AH, AL, soff1, va1);                          \
    split_store(WH, WL, soff0, vw0);                          \
    split_store(WH, WL, soff1, vw1);                          \
} while (0)

__global__ void __launch_bounds__(256, 2) k_gemm_mma(
    const float* __restrict__ A, const float* __restrict__ W,
    const float* __restrict__ bias, float* __restrict__ Cout,
    int K, int N, int mode,
    const float* __restrict__ aux, const float* __restrict__ res,
    int wbatch)
{
    __shared__ bf16 sAh[2][128 * BKP], sAl[2][128 * BKP];
    __shared__ bf16 sWh[2][128 * BKP], sWl[2][128 * BKP];

    int tid = threadIdx.x;
    int lane = tid & 31, wid = tid >> 5;
    int wm = wid & 1, wn = wid >> 1;
    int m0 = blockIdx.y * 128, n0 = blockIdx.x * 128;
    const float* Wp = W + (wbatch ? (size_t)(m0 / TOK) * (size_t)wbatch : 0);

    float acc[16][4];
    #pragma unroll
    for (int i = 0; i < 16; i++)
        #pragma unroll
        for (int j = 0; j < 4; j++) acc[i][j] = 0.f;

    // staging map (round-9): 4 threads per row, 16B each; rows r and r+64
    int row0 = tid >> 2;
    int kg   = tid & 3;
    int soff0 = row0 * BKP + kg * 4;
    int soff1 = (row0 + 64) * BKP + kg * 4;
    const float* Ar0 = A  + (size_t)(m0 + row0)      * K + kg * 4;
    const float* Ar1 = A  + (size_t)(m0 + 64 + row0) * K + kg * 4;
    const float* Wr0 = Wp + (size_t)(n0 + row0)      * K + kg * 4;
    const float* Wr1 = Wp + (size_t)(n0 + 64 + row0) * K + kg * 4;

    // ldmatrix lane addressing: lanes 0-7 rows0-7(klo), 8-15 rows8-15(klo),
    // 16-23 rows0-7(khi +16B), 24-31 rows8-15(khi)
    int ro = ((lane >> 3) & 1) * 8 + (lane & 7);
    int kh = (lane >> 4) * 16;
    uint32_t aoffA = (uint32_t)((wm * 64 + ro) * 48 + kh);
    uint32_t aoffB = (uint32_t)((wn * 32 + ro) * 48 + kh);
    uint32_t aAH = smem_u32(&sAh[0][0]) + aoffA;
    uint32_t aAL = smem_u32(&sAl[0][0]) + aoffA;
    uint32_t aWH = smem_u32(&sWh[0][0]) + aoffB;
    uint32_t aWL = smem_u32(&sWl[0][0]) + aoffB;
    const uint32_t BUFB = 128 * BKP * 2;   // 6144 bytes per buffer

    const int nc = K >> 4;                 // 16 or 64 (always even)
    float4 va0, va1, vw0, vw1;

    // prologue: chunk 0 -> buffer 0
    va0 = *(const float4*)(Ar0); va1 = *(const float4*)(Ar1);
    vw0 = *(const float4*)(Wr0); vw1 = *(const float4*)(Wr1);
    STAGE_STORE(sAh[0], sAl[0], sWh[0], sWl[0]);
    __syncthreads();

    for (int c = 0; c < nc; c += 2) {
        // ---- chunk c (buffer 0); prefetch c+1 (always exists: nc even) ----
        {
            int kc = (c + 1) * 16;
            va0 = *(const float4*)(Ar0 + kc); va1 = *(const float4*)(Ar1 + kc);
            vw0 = *(const float4*)(Wr0 + kc); vw1 = *(const float4*)(Wr1 + kc);
        }
        GEMM_CHUNK(0u);
        STAGE_STORE(sAh[1], sAl[1], sWh[1], sWl[1]);
        __syncthreads();
        // ---- chunk c+1 (buffer 1); prefetch c+2 if any ----
        bool pf = (c + 2 < nc);
        if (pf) {
            int kc = (c + 2) * 16;
            va0 = *(const float4*)(Ar0 + kc); va1 = *(const float4*)(Ar1 + kc);
            vw0 = *(const float4*)(Wr0 + kc); vw1 = *(const float4*)(Wr1 + kc);
        }
        GEMM_CHUNK(BUFB);
        if (pf) STAGE_STORE(sAh[0], sAl[0], sWh[0], sWl[0]);
        __syncthreads();
    }

    // epilogue (round-9 layout)
    #pragma unroll
    for (int mt = 0; mt < 4; mt++) {
        #pragma unroll
        for (int half = 0; half < 2; half++) {
            int m = m0 + wm * 64 + mt * 16 + (lane >> 2) + half * 8;
            float am = (mode >= 3) ? aux[m] : 0.f;
            #pragma unroll
            for (int nt = 0; nt < 4; nt++) {
                int n = n0 + wn * 32 + nt * 8 + (lane & 3) * 2;
                float v0 = acc[mt * 4 + nt][half * 2 + 0];
                float v1 = acc[mt * 4 + nt][half * 2 + 1];
                if (mode == 0)      { v0 += bias[n]; v1 += bias[n + 1]; }
                else if (mode == 1) { v0 += bias[n]; v1 += bias[n + 1];
                                      v0 *= normcdff(v0); v1 *= normcdff(v1); }
                else if (mode == 2) { v0 += bias[n]     + res[(size_t)m * N + n];
                                      v1 += bias[n + 1] + res[(size_t)m * N + n + 1]; }
                else if (mode == 3) { v0 = 0.0625f * (expf(v0 - am) + 1e-4f);
                                      v1 = 0.0625f * (expf(v1 - am) + 1e-4f); }
                else                { v0 = res[(size_t)m * N + n]     + am * v0;
                                      v1 = res[(size_t)m * N + n + 1] + am * v1; }
                *(float2*)&Cout[(size_t)m * N + n] = make_float2(v0, v1);
            }
        }
    }
}

// ---------------------------------------------------------------------------
// K1: transpose [B,C,N] -> [B,N,C] + LayerNorm1 (t = shortcut, h = normed)
// ---------------------------------------------------------------------------
__global__ void __launch_bounds__(256) k_tr_ln(
    const float* __restrict__ x, const float* __restrict__ g,
    const float* __restrict__ bta, float* __restrict__ t, float* __restrict__ h)
{
    __shared__ float tile[32][257];
    int b  = blockIdx.y;
    int n0 = blockIdx.x * 32;
    const float* xb = x + (size_t)b * DIMC * TOK;
    int tx = threadIdx.x & 31, ty = threadIdx.x >> 5;
    #pragma unroll 4
    for (int cc = 0; cc < 32; cc++) {
        int c = cc * 8 + ty;
        tile[tx][c] = xb[(size_t)c * TOK + n0 + tx];
    }
    __syncthreads();
    for (int rep = 0; rep < 4; rep++) {
        int nl = ty + rep * 8;
        float v[8], s = 0.f, sq = 0.f;
        #pragma unroll
        for (int i = 0; i < 8; i++) {
            v[i] = tile[nl][tx + 32 * i];
            s += v[i]; sq += v[i] * v[i];
        }
        #pragma unroll
        for (int o = 16; o; o >>= 1) {
            s  += __shfl_xor_sync(~0u, s,  o);
            sq += __shfl_xor_sync(~0u, sq, o);
        }
        float mu  = s * (1.f / DIMC);
        float var = sq * (1.f / DIMC) - mu * mu;
        float inv = rsqrtf(var + 1e-5f);
        size_t base = ((size_t)b * TOK + n0 + nl) * DIMC;
        #pragma unroll
        for (int i = 0; i < 8; i++) {
            int c = tx + 32 * i;
            t[base + c] = v[i];
            h[base + c] = (v[i] - mu) * inv * g[c] + bta[c];
        }
    }
}

// ---------------------------------------------------------------------------
// LayerNorm2: warp per token.
// ---------------------------------------------------------------------------
__global__ void __launch_bounds__(256) k_ln(
    const float* __restrict__ t, const float* __restrict__ g,
    const float* __restrict__ bta, float* __restrict__ h)
{
    int tok  = blockIdx.x * 8 + (threadIdx.x >> 5);
    int lane = threadIdx.x & 31;
    const float* row = t + (size_t)tok * DIMC;
    float v[8], s = 0.f, sq = 0.f;
    #pragma unroll
    for (int i = 0; i < 8; i++) {
        v[i] = row[lane + 32 * i];
        s += v[i]; sq += v[i] * v[i];
    }
    #pragma unroll
    for (int o = 16; o; o >>= 1) {
        s  += __shfl_xor_sync(~0u, s,  o);
        sq += __shfl_xor_sync(~0u, sq, o);
    }
    float mu  = s * (1.f / DIMC);
    float var = sq * (1.f / DIMC) - mu * mu;
    float inv = rsqrtf(var + 1e-5f);
    float* hr = h + (size_t)tok * DIMC;
    #pragma unroll
    for (int i = 0; i < 8; i++) {
        int c = lane + 32 * i;
        hr[c] = (v[i] - mu) * inv * g[c] + bta[c];
    }
}

// ---------------------------------------------------------------------------
// L2-normalize q,k rows in place + diag = 0.5*||qn||^2.
// ---------------------------------------------------------------------------
__global__ void __launch_bounds__(256) k_norm(
    float* __restrict__ q, float* __restrict__ k,
    float* __restrict__ dq, float* __restrict__ dk)
{
    int tok  = blockIdx.x * 8 + (threadIdx.x >> 5);
    int lane = threadIdx.x & 31;
    for (int s2 = 0; s2 < 2; s2++) {
        float* row = (s2 == 0 ? q : k) + (size_t)tok * DIMC;
        float v[8], sq = 0.f;
        #pragma unroll
        for (int i = 0; i < 8; i++) {
            v[i] = row[lane + 32 * i];
            sq += v[i] * v[i];
        }
        #pragma unroll
        for (int o = 16; o; o >>= 1) sq += __shfl_xor_sync(~0u, sq, o);
        float nrm = sqrtf(sq);
        float sc  = 1.0f / fmaxf(nrm, 5e-5f);
        #pragma unroll
        for (int i = 0; i < 8; i++) row[lane + 32 * i] = v[i] * sc;
        if (lane == 0) (s2 == 0 ? dq : dk)[tok] = 0.5f * sq * sc * sc;
    }
}

// ---------------------------------------------------------------------------
// ctx^T[b][c][f] += sum_n v[b][n][c]*kp[b][n][f]
// 128x128 tile, 8x8 microtile f32x2, ksplit 8 (validated round 15).
// ---------------------------------------------------------------------------
__global__ void __launch_bounds__(256) k_atb(
    const float* __restrict__ V, const float* __restrict__ KP,
    float* __restrict__ CT)
{
    __shared__ __align__(16) float Vs[16][132];
    __shared__ __align__(16) float Ks[16][132];
    int b  = blockIdx.z >> 3;
    int ks = blockIdx.z & 7;
    int c0 = blockIdx.y * 128;
    int f0 = blockIdx.x * 128;
    const float* Vp = V  + (size_t)b * TOK * DIMC;
    const float* Kp = KP + (size_t)b * TOK * DIMC;
    int tid = threadIdx.x;
    int sr = tid >> 4, sc = (tid & 15) * 8;
    int tx = tid & 15, ty = tid >> 4;
    ull acc[8][4];
    #pragma unroll
    for (int i = 0; i < 8; i++)
        #pragma unroll
        for (int j = 0; j < 4; j++) acc[i][j] = 0ull;

    int nbeg = ks * (TOK / 8);
    for (int nt = 0; nt < TOK / 8; nt += 16) {
        int n = nbeg + nt + sr;
        *(float4*)&Vs[sr][sc]     = *(const float4*)&Vp[(size_t)n * DIMC + c0 + sc];
        *(float4*)&Vs[sr][sc + 4] = *(const float4*)&Vp[(size_t)n * DIMC + c0 + sc + 4];
        *(float4*)&Ks[sr][sc]     = *(const float4*)&Kp[(size_t)n * DIMC + f0 + sc];
        *(float4*)&Ks[sr][sc + 4] = *(const float4*)&Kp[(size_t)n * DIMC + f0 + sc + 4];
        __syncthreads();
        #pragma unroll
        for (int kk = 0; kk < 16; kk++) {
            float4 a0 = *(const float4*)&Vs[kk][ty * 4];
            float4 a1 = *(const float4*)&Vs[kk][64 + ty * 4];
            ulonglong2 b0 = *(const ulonglong2*)&Ks[kk][tx * 4];
            ulonglong2 b1 = *(const ulonglong2*)&Ks[kk][64 + tx * 4];
            float a[8] = {a0.x, a0.y, a0.z, a0.w, a1.x, a1.y, a1.z, a1.w};
            ull B[4] = {b0.x, b0.y, b1.x, b1.y};
            #pragma unroll
            for (int i = 0; i < 8; i++) {
                ull ai = pack2f(a[i]);
                #pragma unroll
                for (int j = 0; j < 4; j++) ffma2(acc[i][j], ai, B[j]);
            }
        }
        __syncthreads();
    }
    float* Cb = CT + (size_t)b * DIMC * DIMC;
    #pragma unroll
    for (int i = 0; i < 8; i++) {
        int cr = c0 + ((i < 4) ? (ty * 4 + i) : (64 + ty * 4 + i - 4));
        #pragma unroll
        for (int j = 0; j < 4; j++) {
            int fc = f0 + ((j < 2) ? (tx * 4 + 2 * j) : (64 + tx * 4 + 2 * (j - 2)));
            U2 u; u.u = acc[i][j];
            atomicAdd(&Cb[(size_t)cr * DIMC + fc],     u.f.x);
            atomicAdd(&Cb[(size_t)cr * DIMC + fc + 1], u.f.y);
        }
    }
}

// ---------------------------------------------------------------------------
// small helpers
// ---------------------------------------------------------------------------
__global__ void k_zero(float* __restrict__ p, int n)
{
    int i = blockIdx.x * 256 + threadIdx.x;
    if (i < n) p[i] = 0.f;
}

__global__ void __launch_bounds__(256) k_colsum(
    const float* __restrict__ kp, float* __restrict__ ksum)
{
    int b = blockIdx.y, ch = blockIdx.x;
    int f = threadIdx.x;
    const float* base = kp + ((size_t)b * TOK + ch * 128) * DIMC + f;
    float s = 0.f;
    #pragma unroll 8
    for (int i = 0; i < 128; i++) s += base[(size_t)i * DIMC];
    atomicAdd(&ksum[b * DIMC + f], s);
}

__global__ void __launch_bounds__(256) k_dinv(
    const float* __restrict__ qp, const float* __restrict__ ksum,
    float* __restrict__ di)
{
    int tok  = blockIdx.x * 8 + (threadIdx.x >> 5);
    int lane = threadIdx.x & 31;
    int b = tok >> 12;
    const float* row = qp + (size_t)tok * DIMC;
    const float* ks  = ksum + b * DIMC;
    float s = 0.f;
    #pragma unroll
    for (int i = 0; i < 8; i++) { int c = lane + 32 * i; s += row[c] * ks[c]; }
    #pragma unroll
    for (int o = 16; o; o >>= 1) s += __shfl_xor_sync(~0u, s, o);
    if (lane == 0) di[tok] = 1.0f / s;
}

__global__ void __launch_bounds__(256) k_out_tr(
    const float* __restrict__ t, float* __restrict__ out)
{
    __shared__ float tile[32][33];
    int b  = blockIdx.z;
    int n0 = blockIdx.x * 32;
    int c0 = blockIdx.y * 32;
    int tx = threadIdx.x & 31, ty = threadIdx.x >> 5;
    #pragma unroll
    for (int i = 0; i < 32; i += 8)
        tile[ty + i][tx] = t[((size_t)b * TOK + n0 + ty + i) * DIMC + c0 + tx];
    __syncthreads();
    #pragma unroll
    for (int i = 0; i < 32; i += 8)
        out[((size_t)b * DIMC + c0 + ty + i) * TOK + n0 + tx] = tile[tx][ty + i];
}

// ---------------------------------------------------------------------------
// host launch
// ---------------------------------------------------------------------------
extern "C" void kernel_launch(void* const* d_in, const int* in_sizes, int n_in,
                              void* d_out, int out_size)
{
    const float* x    = (const float*)d_in[0];
    const float* proj = (const float*)d_in[1];
    const float* wq   = (const float*)d_in[2];
    const float* bq   = (const float*)d_in[3];
    const float* wk   = (const float*)d_in[4];
    const float* bk   = (const float*)d_in[5];
    const float* wa   = (const float*)d_in[6];
    const float* ba   = (const float*)d_in[7];
    const float* g1   = (const float*)d_in[8];
    const float* b1   = (const float*)d_in[9];
    const float* g2   = (const float*)d_in[10];
    const float* b2   = (const float*)d_in[11];
    const float* w1   = (const float*)d_in[12];
    const float* fb1  = (const float*)d_in[13];
    const float* w2   = (const float*)d_in[14];
    const float* fb2  = (const float*)d_in[15];
    float* out = (float*)d_out;
    (void)in_sizes; (void)n_in; (void)out_size;

    float *t, *h, *q, *k, *v, *qp, *kp, *m, *ctx, *ksum, *dq, *dk, *di;
    cudaGetSymbolAddress((void**)&t,    g_t);
    cudaGetSymbolAddress((void**)&h,    g_h);
    cudaGetSymbolAddress((void**)&q,    g_q);
    cudaGetSymbolAddress((void**)&k,    g_k);
    cudaGetSymbolAddress((void**)&v,    g_v);
    cudaGetSymbolAddress((void**)&qp,   g_qp);
    cudaGetSymbolAddress((void**)&kp,   g_kp);
    cudaGetSymbolAddress((void**)&m,    g_m);
    cudaGetSymbolAddress((void**)&ctx,  g_ctx);
    cudaGetSymbolAddress((void**)&ksum, g_ksum);
    cudaGetSymbolAddress((void**)&dq,   g_dq);
    cudaGetSymbolAddress((void**)&dk,   g_dk);
    cudaGetSymbolAddress((void**)&di,   g_di);

    // 1. transpose + LN1
    k_tr_ln<<<dim3(TOK / 32, BAT), 256>>>(x, g1, b1, t, h);

    // 2. q, k, v projections
    dim3 gproj(DIMC / 128, MTOT / 128);
    k_gemm_mma<<<gproj, 256>>>(h, wq, bq, q, DIMC, DIMC, 0, nullptr, nullptr, 0);
    k_gemm_mma<<<gproj, 256>>>(h, wk, bk, k, DIMC, DIMC, 0, nullptr, nullptr, 0);
    k_gemm_mma<<<gproj, 256>>>(h, wa, ba, v, DIMC, DIMC, 0, nullptr, nullptr, 0);

    // 3. L2 normalize q,k + diag
    k_norm<<<MTOT / 8, 256>>>(q, k, dq, dk);

    // 4. FAVOR+ feature maps
    k_gemm_mma<<<gproj, 256>>>(q, proj, nullptr, qp, DIMC, DIMC, 3, dq, nullptr, 0);
    k_gemm_mma<<<gproj, 256>>>(k, proj, nullptr, kp, DIMC, DIMC, 3, dk, nullptr, 0);

    // 5. k_sum and ctx^T
    k_zero<<<(BAT * DIMC * DIMC + 255) / 256, 256>>>(ctx, BAT * DIMC * DIMC);
    k_zero<<<(BAT * DIMC + 255) / 256, 256>>>(ksum, BAT * DIMC);
    k_colsum<<<dim3(32, BAT), 256>>>(kp, ksum);
    k_atb<<<dim3(2, 2, BAT * 8), 256>>>(v, kp, ctx);

    // 6. D_inv
    k_dinv<<<MTOT / 8, 256>>>(qp, ksum, di);

    // 7. out = res + D_inv * (qp @ ctx^T^T)  (per-batch W = ctx)
    k_gemm_mma<<<gproj, 256>>>(qp, ctx, nullptr, t, DIMC, DIMC, 4, di, t, DIMC * DIMC);

    // 8. LN2 + MLP
    k_ln<<<MTOT / 8, 256>>>(t, g2, b2, h);
    k_gemm_mma<<<dim3(HID / 128, MTOT / 128), 256>>>(h, w1, fb1, m, DIMC, HID, 1,
                                                     nullptr, nullptr, 0);
    k_gemm_mma<<<dim3(DIMC / 128, MTOT / 128), 256>>>(m, w2, fb2, t, HID, DIMC, 2,
                                                      nullptr, t, 0);

    // 9. transpose back
    k_out_tr<<<dim3(TOK / 32, DIMC / 32, BAT), 256>>>(t, out);
}

// round 17
// speedup vs baseline: 1.4162x; 1.0779x over previous
#include <cuda_runtime.h>
#include <cuda_bf16.h>
#include <math.h>
#include <stdint.h>

// ---------------------------------------------------------------------------
// ENL transformer block (Performer / FAVOR+), mma.sync bf16-split GEMMs.
// Round-9 GEMM core (proven) + 128x128 k_atb (proven) + layout fusions.
// B=8, C=256, N=4096 tokens/batch, F=256, MLP hidden=1024.
// ---------------------------------------------------------------------------

#define TOK   4096
#define BAT   8
#define DIMC  256
#define HID   1024
#define MTOT  (BAT * TOK)

typedef unsigned long long ull;

// ------------------------------ scratch ------------------------------------
__device__ float g_t   [(size_t)MTOT * DIMC];
__device__ float g_h   [(size_t)MTOT * DIMC];
__device__ float g_qkv [(size_t)MTOT * 768];          // q|k|v per row
__device__ float g_qkn [(size_t)2 * MTOT * DIMC];     // qn | kn contiguous
__device__ float g_qkp [(size_t)2 * MTOT * DIMC];     // qp | kp contiguous
__device__ float g_m   [(size_t)MTOT * HID];
__device__ float g_ctx [(size_t)BAT * DIMC * DIMC];
__device__ float g_ksum[BAT * DIMC];
__device__ float g_dqk [(size_t)2 * MTOT];            // dq | dk
__device__ float g_di  [(size_t)MTOT];
__device__ float g_wqkv[768 * DIMC];                  // wq|wk|wa concat (fp32)
__device__ float g_bqkv[768];

// ---------------------------- packed fp32x2 (k_atb) ------------------------
__device__ __forceinline__ void ffma2(ull& d, ull a, ull b) {
    asm("fma.rn.f32x2 %0, %1, %2, %0;" : "+l"(d) : "l"(a), "l"(b));
}
__device__ __forceinline__ ull pack2f(float x) {
    ull r; asm("mov.b64 %0, {%1, %1};" : "=l"(r) : "f"(x)); return r;
}
union U2 { ull u; float2 f; };

// ---------------------------- bf16 helpers ---------------------------------
__device__ __forceinline__ uint32_t bf2pack(float lo, float hi) {
    uint32_t r;
    asm("cvt.rn.bf16x2.f32 %0, %1, %2;" : "=r"(r) : "f"(hi), "f"(lo));
    return r;
}

// mma.sync m16n8k16 row.col f32 += bf16*bf16
__device__ __forceinline__ void mma16816v(float* c, const uint32_t* a,
                                          const uint32_t* b) {
    asm volatile(
        "mma.sync.aligned.m16n8k16.row.col.f32.bf16.bf16.f32 "
        "{%0,%1,%2,%3}, {%4,%5,%6,%7}, {%8,%9}, {%0,%1,%2,%3};"
        : "+f"(c[0]), "+f"(c[1]), "+f"(c[2]), "+f"(c[3])
        : "r"(a[0]), "r"(a[1]), "r"(a[2]), "r"(a[3]), "r"(b[0]), "r"(b[1]));
}

// ---------------------------------------------------------------------------
// Round-9 GEMM (verbatim core): C[M,N] = epi( A[M,K] @ W[N,K]^T ),
// bf16 hi/lo 3-pass split. CTA 128x128, BK=16, 8 warps (64x32),
// static smem BKP=24, register-staged double buffer, scalar-LDS fragments.
// modes: 0 bias | 1 bias+gelu | 2 bias+res | 3 featuremap | 4 res+aux*acc
// ---------------------------------------------------------------------------
#define BKP 24   // padded smem row stride (bf16)

__device__ __forceinline__ void split_store(__nv_bfloat16* hi, __nv_bfloat16* lo,
                                            int off, float4 v) {
    __nv_bfloat16 h0 = __float2bfloat16(v.x);
    __nv_bfloat16 h1 = __float2bfloat16(v.y);
    __nv_bfloat16 h2 = __float2bfloat16(v.z);
    __nv_bfloat16 h3 = __float2bfloat16(v.w);
    float l0 = v.x - __bfloat162float(h0);
    float l1 = v.y - __bfloat162float(h1);
    float l2 = v.z - __bfloat162float(h2);
    float l3 = v.w - __bfloat162float(h3);
    uint32_t hp0 = ((uint32_t)__bfloat16_as_ushort(h1) << 16) | __bfloat16_as_ushort(h0);
    uint32_t hp1 = ((uint32_t)__bfloat16_as_ushort(h3) << 16) | __bfloat16_as_ushort(h2);
    *(uint2*)(hi + off) = make_uint2(hp0, hp1);
    *(uint2*)(lo + off) = make_uint2(bf2pack(l0, l1), bf2pack(l2, l3));
}

__device__ __forceinline__ void ld_afrag(uint32_t af[4][4],
                                         const __nv_bfloat16* S, int ar, int ac) {
    #pragma unroll
    for (int mt = 0; mt < 4; mt++) {
        const __nv_bfloat16* p = S + (ar + mt * 16) * BKP + ac;
        af[mt][0] = *(const uint32_t*)(p);
        af[mt][1] = *(const uint32_t*)(p + 8 * BKP);
        af[mt][2] = *(const uint32_t*)(p + 8);
        af[mt][3] = *(const uint32_t*)(p + 8 * BKP + 8);
    }
}
__device__ __forceinline__ void ld_bfrag(uint32_t bf[4][2],
                                         const __nv_bfloat16* S, int br, int ac) {
    #pragma unroll
    for (int nt = 0; nt < 4; nt++) {
        const __nv_bfloat16* p = S + (br + nt * 8) * BKP + ac;
        bf[nt][0] = *(const uint32_t*)(p);
        bf[nt][1] = *(const uint32_t*)(p + 8);
    }
}
__device__ __forceinline__ void mma_all(float acc[16][4],
                                        uint32_t af[4][4], uint32_t bf[4][2]) {
    #pragma unroll
    for (int mt = 0; mt < 4; mt++)
        #pragma unroll
        for (int nt = 0; nt < 4; nt++)
            mma16816v(acc[mt * 4 + nt], af[mt], bf[nt]);
}

__global__ void __launch_bounds__(256, 2) k_gemm_mma(
    const float* __restrict__ A, const float* __restrict__ W,
    const float* __restrict__ bias, float* __restrict__ Cout,
    int K, int N, int mode,
    const float* __restrict__ aux, const float* __restrict__ res,
    int wbatch)
{
    __shared__ __nv_bfloat16 sAh[2][128 * BKP], sAl[2][128 * BKP];
    __shared__ __nv_bfloat16 sWh[2][128 * BKP], sWl[2][128 * BKP];

    int tid = threadIdx.x;
    int lane = tid & 31, wid = tid >> 5;
    int wm = wid & 1, wn = wid >> 1;            // warp tile (wm*64, wn*32)
    int m0 = blockIdx.y * 128, n0 = blockIdx.x * 128;
    const float* Wp = W + (wbatch ? (size_t)(m0 / TOK) * (size_t)wbatch : 0);

    float acc[16][4];
    #pragma unroll
    for (int i = 0; i < 16; i++)
        #pragma unroll
        for (int j = 0; j < 4; j++) acc[i][j] = 0.f;

    int row0 = tid >> 2;        // 0..63 (also +64)
    int kg   = tid & 3;         // float4 index within BK=16
    int soff0 = row0 * BKP + kg * 4;
    int soff1 = (row0 + 64) * BKP + kg * 4;

    int ar = wm * 64 + (lane >> 2);
    int br = wn * 32 + (lane >> 2);
    int ac = (lane & 3) * 2;

    const int nc = K >> 4;
    float4 a0, a1, w0, w1;

    // prologue: chunk 0
    a0 = *(const float4*)&A [(size_t)(m0 + row0)      * K + kg * 4];
    a1 = *(const float4*)&A [(size_t)(m0 + row0 + 64) * K + kg * 4];
    w0 = *(const float4*)&Wp[(size_t)(n0 + row0)      * K + kg * 4];
    w1 = *(const float4*)&Wp[(size_t)(n0 + row0 + 64) * K + kg * 4];
    split_store(sAh[0], sAl[0], soff0, a0);
    split_store(sAh[0], sAl[0], soff1, a1);
    split_store(sWh[0], sWl[0], soff0, w0);
    split_store(sWh[0], sWl[0], soff1, w1);
    __syncthreads();

    for (int c = 0; c < nc; c++) {
        int buf = c & 1;
        if (c + 1 < nc) {
            int kc = (c + 1) * 16;
            a0 = *(const float4*)&A [(size_t)(m0 + row0)      * K + kc + kg * 4];
            a1 = *(const float4*)&A [(size_t)(m0 + row0 + 64) * K + kc + kg * 4];
            w0 = *(const float4*)&Wp[(size_t)(n0 + row0)      * K + kc + kg * 4];
            w1 = *(const float4*)&Wp[(size_t)(n0 + row0 + 64) * K + kc + kg * 4];
        }
        {
            uint32_t af[4][4], bf_[4][2];
            ld_afrag(af, sAh[buf], ar, ac);      // A-hi
            ld_bfrag(bf_, sWh[buf], br, ac);     // * W-hi
            mma_all(acc, af, bf_);
            ld_bfrag(bf_, sWl[buf], br, ac);     // * W-lo (reuse A-hi frags)
            mma_all(acc, af, bf_);
            ld_afrag(af, sAl[buf], ar, ac);      // A-lo
            ld_bfrag(bf_, sWh[buf], br, ac);     // * W-hi
            mma_all(acc, af, bf_);
        }
        if (c + 1 < nc) {
            int nb = (c + 1) & 1;
            split_store(sAh[nb], sAl[nb], soff0, a0);
            split_store(sAh[nb], sAl[nb], soff1, a1);
            split_store(sWh[nb], sWl[nb], soff0, w0);
            split_store(sWh[nb], sWl[nb], soff1, w1);
        }
        __syncthreads();
    }

    // epilogue
    #pragma unroll
    for (int mt = 0; mt < 4; mt++) {
        #pragma unroll
        for (int half = 0; half < 2; half++) {
            int m = m0 + wm * 64 + mt * 16 + (lane >> 2) + half * 8;
            float am = (mode >= 3) ? aux[m] : 0.f;
            #pragma unroll
            for (int nt = 0; nt < 4; nt++) {
                int n = n0 + wn * 32 + nt * 8 + (lane & 3) * 2;
                float v0 = acc[mt * 4 + nt][half * 2 + 0];
                float v1 = acc[mt * 4 + nt][half * 2 + 1];
                if (mode == 0)      { v0 += bias[n]; v1 += bias[n + 1]; }
                else if (mode == 1) { v0 += bias[n]; v1 += bias[n + 1];
                                      v0 *= normcdff(v0); v1 *= normcdff(v1); }
                else if (mode == 2) { v0 += bias[n]     + res[(size_t)m * N + n];
                                      v1 += bias[n + 1] + res[(size_t)m * N + n + 1]; }
                else if (mode == 3) { v0 = 0.0625f * (expf(v0 - am) + 1e-4f);
                                      v1 = 0.0625f * (expf(v1 - am) + 1e-4f); }
                else                { v0 = res[(size_t)m * N + n]     + am * v0;
                                      v1 = res[(size_t)m * N + n + 1] + am * v1; }
                *(float2*)&Cout[(size_t)m * N + n] = make_float2(v0, v1);
            }
        }
    }
}

// ---------------------------------------------------------------------------
// concat wq|wk|wa -> wqkv[768][256] and bq|bk|ba -> bqkv (fp32 copies)
// ---------------------------------------------------------------------------
__global__ void k_cat(const float* __restrict__ wq, const float* __restrict__ wk,
                      const float* __restrict__ wa, const float* __restrict__ bq,
                      const float* __restrict__ bk, const float* __restrict__ ba,
                      float* __restrict__ wqkv, float* __restrict__ bqkv)
{
    int i = blockIdx.x * 256 + threadIdx.x;
    if (i < 196608) {
        const float* src = (i < 65536) ? wq : (i < 131072) ? wk : wa;
        wqkv[i] = src[i & 65535];
    } else if (i < 197376) {
        int li = i - 196608;
        bqkv[li] = (li < 256) ? bq[li] : (li < 512) ? bk[li - 256] : ba[li - 512];
    }
}

// ---------------------------------------------------------------------------
// K1: transpose [B,C,N] -> [B,N,C] + LayerNorm1 (t = shortcut, h = normed)
// ---------------------------------------------------------------------------
__global__ void __launch_bounds__(256) k_tr_ln(
    const float* __restrict__ x, const float* __restrict__ g,
    const float* __restrict__ bta, float* __restrict__ t, float* __restrict__ h)
{
    __shared__ float tile[32][257];
    int b  = blockIdx.y;
    int n0 = blockIdx.x * 32;
    const float* xb = x + (size_t)b * DIMC * TOK;
    int tx = threadIdx.x & 31, ty = threadIdx.x >> 5;
    #pragma unroll 4
    for (int cc = 0; cc < 32; cc++) {
        int c = cc * 8 + ty;
        tile[tx][c] = xb[(size_t)c * TOK + n0 + tx];
    }
    __syncthreads();
    for (int rep = 0; rep < 4; rep++) {
        int nl = ty + rep * 8;
        float v[8], s = 0.f, sq = 0.f;
        #pragma unroll
        for (int i = 0; i < 8; i++) {
            v[i] = tile[nl][tx + 32 * i];
            s += v[i]; sq += v[i] * v[i];
        }
        #pragma unroll
        for (int o = 16; o; o >>= 1) {
            s  += __shfl_xor_sync(~0u, s,  o);
            sq += __shfl_xor_sync(~0u, sq, o);
        }
        float mu  = s * (1.f / DIMC);
        float var = sq * (1.f / DIMC) - mu * mu;
        float inv = rsqrtf(var + 1e-5f);
        size_t base = ((size_t)b * TOK + n0 + nl) * DIMC;
        #pragma unroll
        for (int i = 0; i < 8; i++) {
            int c = tx + 32 * i;
            t[base + c] = v[i];
            h[base + c] = (v[i] - mu) * inv * g[c] + bta[c];
        }
    }
}

// ---------------------------------------------------------------------------
// LayerNorm2: warp per token.
// ---------------------------------------------------------------------------
__global__ void __launch_bounds__(256) k_ln(
    const float* __restrict__ t, const float* __restrict__ g,
    const float* __restrict__ bta, float* __restrict__ h)
{
    int tok  = blockIdx.x * 8 + (threadIdx.x >> 5);
    int lane = threadIdx.x & 31;
    const float* row = t + (size_t)tok * DIMC;
    float v[8], s = 0.f, sq = 0.f;
    #pragma unroll
    for (int i = 0; i < 8; i++) {
        v[i] = row[lane + 32 * i];
        s += v[i]; sq += v[i] * v[i];
    }
    #pragma unroll
    for (int o = 16; o; o >>= 1) {
        s  += __shfl_xor_sync(~0u, s,  o);
        sq += __shfl_xor_sync(~0u, sq, o);
    }
    float mu  = s * (1.f / DIMC);
    float var = sq * (1.f / DIMC) - mu * mu;
    float inv = rsqrtf(var + 1e-5f);
    float* hr = h + (size_t)tok * DIMC;
    #pragma unroll
    for (int i = 0; i < 8; i++) {
        int c = lane + 32 * i;
        hr[c] = (v[i] - mu) * inv * g[c] + bta[c];
    }
}

// ---------------------------------------------------------------------------
// L2-normalize q,k from qkv (pitch 768) -> qkn (qn | kn, pitch 256) + diag
// ---------------------------------------------------------------------------
__global__ void __launch_bounds__(256) k_norm(
    const float* __restrict__ qkv, float* __restrict__ qkn,
    float* __restrict__ dqk)
{
    int tok  = blockIdx.x * 8 + (threadIdx.x >> 5);
    int lane = threadIdx.x & 31;
    for (int s2 = 0; s2 < 2; s2++) {
        const float* row = qkv + (size_t)tok * 768 + s2 * 256;
        float* orow = qkn + ((size_t)s2 * MTOT + tok) * DIMC;
        float v[8], sq = 0.f;
        #pragma unroll
        for (int i = 0; i < 8; i++) {
            v[i] = row[lane + 32 * i];
            sq += v[i] * v[i];
        }
        #pragma unroll
        for (int o = 16; o; o >>= 1) sq += __shfl_xor_sync(~0u, sq, o);
        float nrm = sqrtf(sq);
        float sc  = 1.0f / fmaxf(nrm, 5e-5f);
        #pragma unroll
        for (int i = 0; i < 8; i++) orow[lane + 32 * i] = v[i] * sc;
        if (lane == 0) dqk[(size_t)s2 * MTOT + tok] = 0.5f * sq * sc * sc;
    }
}

// ---------------------------------------------------------------------------
// ctx^T[b][c][f] += sum_n v[b][n][c]*kp[b][n][f]
// 128x128 tile, 8x8 microtile f32x2, ksplit 8. V from qkv (pitch 768, +512).
// ---------------------------------------------------------------------------
__global__ void __launch_bounds__(256) k_atb(
    const float* __restrict__ QKV, const float* __restrict__ KP,
    float* __restrict__ CT)
{
    __shared__ __align__(16) float Vs[16][132];
    __shared__ __align__(16) float Ks[16][132];
    int b  = blockIdx.z >> 3;
    int ks = blockIdx.z & 7;
    int c0 = blockIdx.y * 128;
    int f0 = blockIdx.x * 128;
    const float* Vp = QKV + (size_t)b * TOK * 768 + 512;
    const float* Kp = KP  + (size_t)b * TOK * DIMC;
    int tid = threadIdx.x;
    int sr = tid >> 4, sc = (tid & 15) * 8;
    int tx = tid & 15, ty = tid >> 4;
    ull acc[8][4];
    #pragma unroll
    for (int i = 0; i < 8; i++)
        #pragma unroll
        for (int j = 0; j < 4; j++) acc[i][j] = 0ull;

    int nbeg = ks * (TOK / 8);
    for (int nt = 0; nt < TOK / 8; nt += 16) {
        int n = nbeg + nt + sr;
        *(float4*)&Vs[sr][sc]     = *(const float4*)&Vp[(size_t)n * 768 + c0 + sc];
        *(float4*)&Vs[sr][sc + 4] = *(const float4*)&Vp[(size_t)n * 768 + c0 + sc + 4];
        *(float4*)&Ks[sr][sc]     = *(const float4*)&Kp[(size_t)n * DIMC + f0 + sc];
        *(float4*)&Ks[sr][sc + 4] = *(const float4*)&Kp[(size_t)n * DIMC + f0 + sc + 4];
        __syncthreads();
        #pragma unroll
        for (int kk = 0; kk < 16; kk++) {
            float4 a0 = *(const float4*)&Vs[kk][ty * 4];
            float4 a1 = *(const float4*)&Vs[kk][64 + ty * 4];
            ulonglong2 b0 = *(const ulonglong2*)&Ks[kk][tx * 4];
            ulonglong2 b1 = *(const ulonglong2*)&Ks[kk][64 + tx * 4];
            float a[8] = {a0.x, a0.y, a0.z, a0.w, a1.x, a1.y, a1.z, a1.w};
            ull B[4] = {b0.x, b0.y, b1.x, b1.y};
            #pragma unroll
            for (int i = 0; i < 8; i++) {
                ull ai = pack2f(a[i]);
                #pragma unroll
                for (int j = 0; j < 4; j++) ffma2(acc[i][j], ai, B[j]);
            }
        }
        __syncthreads();
    }
    float* Cb = CT + (size_t)b * DIMC * DIMC;
    #pragma unroll
    for (int i = 0; i < 8; i++) {
        int cr = c0 + ((i < 4) ? (ty * 4 + i) : (64 + ty * 4 + i - 4));
        #pragma unroll
        for (int j = 0; j < 4; j++) {
            int fc = f0 + ((j < 2) ? (tx * 4 + 2 * j) : (64 + tx * 4 + 2 * (j - 2)));
            U2 u; u.u = acc[i][j];
            atomicAdd(&Cb[(size_t)cr * DIMC + fc],     u.f.x);
            atomicAdd(&Cb[(size_t)cr * DIMC + fc + 1], u.f.y);
        }
    }
}

// ---------------------------------------------------------------------------
// small helpers
// ---------------------------------------------------------------------------
__global__ void k_zero(float* __restrict__ p, int n)
{
    int i = blockIdx.x * 256 + threadIdx.x;
    if (i < n) p[i] = 0.f;
}

__global__ void __launch_bounds__(256) k_colsum(
    const float* __restrict__ kp, float* __restrict__ ksum)
{
    int b = blockIdx.y, ch = blockIdx.x;
    int f = threadIdx.x;
    const float* base = kp + ((size_t)b * TOK + ch * 128) * DIMC + f;
    float s = 0.f;
    #pragma unroll 8
    for (int i = 0; i < 128; i++) s += base[(size_t)i * DIMC];
    atomicAdd(&ksum[b * DIMC + f], s);
}

__global__ void __launch_bounds__(256) k_dinv(
    const float* __restrict__ qp, const float* __restrict__ ksum,
    float* __restrict__ di)
{
    int tok  = blockIdx.x * 8 + (threadIdx.x >> 5);
    int lane = threadIdx.x & 31;
    int b = tok >> 12;
    const float* row = qp + (size_t)tok * DIMC;
    const float* ks  = ksum + b * DIMC;
    float s = 0.f;
    #pragma unroll
    for (int i = 0; i < 8; i++) { int c = lane + 32 * i; s += row[c] * ks[c]; }
    #pragma unroll
    for (int o = 16; o; o >>= 1) s += __shfl_xor_sync(~0u, s, o);
    if (lane == 0) di[tok] = 1.0f / s;
}

__global__ void __launch_bounds__(256) k_out_tr(
    const float* __restrict__ t, float* __restrict__ out)
{
    __shared__ float tile[32][33];
    int b  = blockIdx.z;
    int n0 = blockIdx.x * 32;
    int c0 = blockIdx.y * 32;
    int tx = threadIdx.x & 31, ty = threadIdx.x >> 5;
    #pragma unroll
    for (int i = 0; i < 32; i += 8)
        tile[ty + i][tx] = t[((size_t)b * TOK + n0 + ty + i) * DIMC + c0 + tx];
    __syncthreads();
    #pragma unroll
    for (int i = 0; i < 32; i += 8)
        out[((size_t)b * DIMC + c0 + ty + i) * TOK + n0 + tx] = tile[tx][ty + i];
}

// ---------------------------------------------------------------------------
// host launch
// ---------------------------------------------------------------------------
extern "C" void kernel_launch(void* const* d_in, const int* in_sizes, int n_in,
                              void* d_out, int out_size)
{
    const float* x    = (const float*)d_in[0];
    const float* proj = (const float*)d_in[1];
    const float* wq   = (const float*)d_in[2];
    const float* bq   = (const float*)d_in[3];
    const float* wk   = (const float*)d_in[4];
    const float* bk   = (const float*)d_in[5];
    const float* wa   = (const float*)d_in[6];
    const float* ba   = (const float*)d_in[7];
    const float* g1   = (const float*)d_in[8];
    const float* b1   = (const float*)d_in[9];
    const float* g2   = (const float*)d_in[10];
    const float* b2   = (const float*)d_in[11];
    const float* w1   = (const float*)d_in[12];
    const float* fb1  = (const float*)d_in[13];
    const float* w2   = (const float*)d_in[14];
    const float* fb2  = (const float*)d_in[15];
    float* out = (float*)d_out;
    (void)in_sizes; (void)n_in; (void)out_size;

    float *t, *h, *qkv, *qkn, *qkp, *m, *ctx, *ksum, *dqk, *di, *wqkv, *bqkv;
    cudaGetSymbolAddress((void**)&t,    g_t);
    cudaGetSymbolAddress((void**)&h,    g_h);
    cudaGetSymbolAddress((void**)&qkv,  g_qkv);
    cudaGetSymbolAddress((void**)&qkn,  g_qkn);
    cudaGetSymbolAddress((void**)&qkp,  g_qkp);
    cudaGetSymbolAddress((void**)&m,    g_m);
    cudaGetSymbolAddress((void**)&ctx,  g_ctx);
    cudaGetSymbolAddress((void**)&ksum, g_ksum);
    cudaGetSymbolAddress((void**)&dqk,  g_dqk);
    cudaGetSymbolAddress((void**)&di,   g_di);
    cudaGetSymbolAddress((void**)&wqkv, g_wqkv);
    cudaGetSymbolAddress((void**)&bqkv, g_bqkv);

    float* kp = qkp + (size_t)MTOT * DIMC;

    // 0. concat qkv weights/biases (fp32)
    k_cat<<<771, 256>>>(wq, wk, wa, bq, bk, ba, wqkv, bqkv);

    // 1. transpose + LN1
    k_tr_ln<<<dim3(TOK / 32, BAT), 256>>>(x, g1, b1, t, h);

    // 2. fused QKV projection (N=768)
    k_gemm_mma<<<dim3(6, MTOT / 128), 256>>>(h, wqkv, bqkv, qkv,
                                             DIMC, 768, 0, nullptr, nullptr, 0);

    // 3. L2 normalize q,k -> qkn (contiguous) + diag
    k_norm<<<MTOT / 8, 256>>>(qkv, qkn, dqk);

    // 4. fused FAVOR+ feature maps (M = 2*MTOT) -> qkp (qp | kp)
    k_gemm_mma<<<dim3(2, 2 * MTOT / 128), 256>>>(qkn, proj, nullptr, qkp,
                                                 DIMC, DIMC, 3, dqk, nullptr, 0);

    // 5. k_sum and ctx^T
    k_zero<<<(BAT * DIMC * DIMC + 255) / 256, 256>>>(ctx, BAT * DIMC * DIMC);
    k_zero<<<(BAT * DIMC + 255) / 256, 256>>>(ksum, BAT * DIMC);
    k_colsum<<<dim3(32, BAT), 256>>>(kp, ksum);
    k_atb<<<dim3(2, 2, BAT * 8), 256>>>(qkv, kp, ctx);

    // 6. D_inv
    k_dinv<<<MTOT / 8, 256>>>(qkp, ksum, di);

    // 7. out = res + D_inv * (qp @ ctx^T^T)  (per-batch W = ctx)
    k_gemm_mma<<<dim3(2, MTOT / 128), 256>>>(qkp, ctx, nullptr, t,
                                             DIMC, DIMC, 4, di, t, DIMC * DIMC);

    // 8. LN2 + MLP
    k_ln<<<MTOT / 8, 256>>>(t, g2, b2, h);
    k_gemm_mma<<<dim3(HID / 128, MTOT / 128), 256>>>(h, w1, fb1, m, DIMC, HID, 1,
                                                     nullptr, nullptr, 0);
    k_gemm_mma<<<dim3(DIMC / 128, MTOT / 128), 256>>>(m, w2, fb2, t, HID, DIMC, 2,
                                                      nullptr, t, 0);

    // 9. transpose back
    k_out_tr<<<dim3(TOK / 32, DIMC / 32, BAT), 256>>>(t, out);
}